// round 6
// baseline (speedup 1.0000x reference)
#include <cuda_runtime.h>
#include <stdint.h>

// ---------------------------------------------------------------------------
// HarmonicFullyConnectedTensorProduct (lmax=2, MUL=64, BATCH=1024, 11 paths)
// v4: W staged via cp.async into smem (latency off critical path),
//     Phase A slimmed (reg-cached a/b, paired C loads, merged-o paths,
//     path-split across thread groups), 3 CTAs/SM.
// ---------------------------------------------------------------------------

typedef unsigned long long ull;

#define NP 11
__host__ __device__ constexpr int PL1[NP]  = {0,0,0,1,1,1,1,2,2,2,2};
__host__ __device__ constexpr int PL2[NP]  = {0,1,2,0,1,1,2,0,1,2,2};
__host__ __device__ constexpr int PL3[NP]  = {0,1,2,1,0,2,1,2,1,0,2};
__host__ __device__ constexpr int XOFF[3]  = {0,1,4};
// t-record per-path blocks padded even (stride 46)
__host__ __device__ constexpr int TOP[NP]  = {0,2,6,12,16,18,24,28,34,38,40};
// padded C layout: per (m,n) slot = m3+(m3&1) ulls; path bases (ull units)
__host__ __device__ constexpr int CPB[NP]  = {0,2,14,44,56,74,128,188,218,278,328};
#define C_TOT 478

#define ZT 16
#define ZP 8
#define UT 8
#define VT 8
#define NVC 8
#define TREC 46
#define XSTR 10

// smem layout (ull units)
#define X1_OFF 0                    // 64 rec * 10 = 640
#define X2_OFF 640                  // 64 rec * 10 = 640
#define C_OFF  1280                 // 480 (478 used)
#define T_OFF  1760                 // 64 rec * 46 = 2944
#define W_OFF  4704                 // 2816 ull = 5632 floats
#define SMEM_ULL  7520
#define SMEM_BYTES (SMEM_ULL*8)     // 60160 -> 3 CTAs/SM

// W transposed: [u][v][p][w] floats
__device__ float g_Wt[64 * 64 * NP * 64];

// ---------------- packed f32x2 helpers ----------------
__device__ __forceinline__ ull pk(float lo, float hi) {
    ull r;
    asm("mov.b64 %0, {%1, %2};" : "=l"(r) : "r"(__float_as_uint(lo)), "r"(__float_as_uint(hi)));
    return r;
}
__device__ __forceinline__ void unpk(ull v, float& lo, float& hi) {
    unsigned a, b;
    asm("mov.b64 {%0, %1}, %2;" : "=r"(a), "=r"(b) : "l"(v));
    lo = __uint_as_float(a); hi = __uint_as_float(b);
}
__device__ __forceinline__ ull fma2(ull a, ull b, ull c) {
    ull d;
    asm("fma.rn.f32x2 %0, %1, %2, %3;" : "=l"(d) : "l"(a), "l"(b), "l"(c));
    return d;
}
__device__ __forceinline__ ull mul2(ull a, ull b) {
    ull d;
    asm("mul.rn.f32x2 %0, %1, %2;" : "=l"(d) : "l"(a), "l"(b));
    return d;
}
__device__ __forceinline__ uint32_t s2u32(const void* p) {
    uint32_t a;
    asm("{ .reg .u64 t; cvta.to.shared.u64 t, %1; cvt.u32.u64 %0, t; }" : "=r"(a) : "l"(p));
    return a;
}
__device__ __forceinline__ void cpasync16(uint32_t dst, const void* src) {
    asm volatile("cp.async.cg.shared.global [%0], [%1], 16;" :: "r"(dst), "l"(src));
}
__device__ __forceinline__ void cpcommit() {
    asm volatile("cp.async.commit_group;");
}
__device__ __forceinline__ void cpwait0() {
    asm volatile("cp.async.wait_group 0;" ::: "memory");
}

// ---------------- W transpose ----------------
__global__ void transpose_W_kernel(const float* __restrict__ W) {
    int idx = blockIdx.x * 256 + threadIdx.x;   // g_Wt index, w fastest
    int w  = idx & 63;
    int p  = (idx >> 6) % NP;
    int uv = idx / (NP * 64);
    g_Wt[idx] = W[(((p << 6) + w) << 12) + uv];
}

// ---------------- Phase A: single path ----------------
template <int P>
__device__ __forceinline__ void pathA(const ull* a, const ull* b,
                                      const ull* __restrict__ c2, ull* trec) {
    constexpr int L1 = PL1[P], L2 = PL2[P], L3 = PL3[P];
    constexpr int M1 = 2*L1+1, M2 = 2*L2+1, M3 = 2*L3+1;
    constexpr int O1 = XOFF[L1], O2 = XOFF[L2];
    constexpr int CB = CPB[P], SLOT = M3 + (M3 & 1), TO = TOP[P];
    ull t[M3];
#pragma unroll
    for (int k = 0; k < M3; k++) t[k] = 0ull;
#pragma unroll
    for (int m = 0; m < M1; m++) {
        ull am = a[O1 + m];
#pragma unroll
        for (int n = 0; n < M2; n++) {
            ull o = mul2(am, b[O2 + n]);
            const int base = CB + (m*M2 + n)*SLOT;
#pragma unroll
            for (int kk = 0; kk < M3/2; kk++) {
                ulonglong2 q = *(const ulonglong2*)(c2 + base + 2*kk);
                t[2*kk]   = fma2(o, q.x, t[2*kk]);
                t[2*kk+1] = fma2(o, q.y, t[2*kk+1]);
            }
            if (M3 & 1)
                t[M3-1] = fma2(o, c2[base + M3 - 1], t[M3-1]);
        }
    }
#pragma unroll
    for (int kk = 0; kk < M3/2; kk++) {
        ulonglong2 s; s.x = t[2*kk]; s.y = t[2*kk+1];
        *(ulonglong2*)(trec + TO + 2*kk) = s;
    }
    if (M3 & 1) {
        ulonglong2 s; s.x = t[M3-1]; s.y = t[M3-1];
        *(ulonglong2*)(trec + TO + M3 - 1) = s;
    }
}

// ---------------- Phase A: merged pair (PA has m3=1, PB has m3=5, same l1,l2) ----
template <int PA, int PB>
__device__ __forceinline__ void pathA2(const ull* a, const ull* b,
                                       const ull* __restrict__ c2, ull* trec) {
    constexpr int L1 = PL1[PA], L2 = PL2[PA];
    constexpr int M1 = 2*L1+1, M2 = 2*L2+1;
    constexpr int O1 = XOFF[L1], O2 = XOFF[L2];
    constexpr int CA = CPB[PA], CB = CPB[PB];
    ull tA = 0ull;
    ull tB[5] = {0ull,0ull,0ull,0ull,0ull};
#pragma unroll
    for (int m = 0; m < M1; m++) {
        ull am = a[O1 + m];
#pragma unroll
        for (int n = 0; n < M2; n++) {
            const int mn = m*M2 + n;
            ull o = mul2(am, b[O2 + n]);
            tA = fma2(o, c2[CA + mn*2], tA);
            const ull* cb = c2 + CB + mn*6;
            ulonglong2 q0 = *(const ulonglong2*)(cb);
            ulonglong2 q1 = *(const ulonglong2*)(cb + 2);
            ull c4 = cb[4];
            tB[0] = fma2(o, q0.x, tB[0]);
            tB[1] = fma2(o, q0.y, tB[1]);
            tB[2] = fma2(o, q1.x, tB[2]);
            tB[3] = fma2(o, q1.y, tB[3]);
            tB[4] = fma2(o, c4,  tB[4]);
        }
    }
    { ulonglong2 s; s.x = tA; s.y = tA; *(ulonglong2*)(trec + TOP[PA]) = s; }
    { ulonglong2 s; s.x = tB[0]; s.y = tB[1]; *(ulonglong2*)(trec + TOP[PB]    ) = s; }
    { ulonglong2 s; s.x = tB[2]; s.y = tB[3]; *(ulonglong2*)(trec + TOP[PB] + 2) = s; }
    { ulonglong2 s; s.x = tB[4]; s.y = tB[4]; *(ulonglong2*)(trec + TOP[PB] + 4) = s; }
}

// ---------------- Phase B: one path, 4 w per thread (W from smem) ----------------
template <int P>
__device__ __forceinline__ void pathB(const float* __restrict__ wv,
                                      const ull* __restrict__ tp,
                                      ull (&acc)[4][9]) {
    constexpr int M3 = 2*PL3[P]+1, TO = TOP[P], KO = XOFF[PL3[P]];
    float4 wf = *(const float4*)(wv + P * 64);
    ull w0 = pk(wf.x, wf.x);
    ull w1 = pk(wf.y, wf.y);
    ull w2 = pk(wf.z, wf.z);
    ull w3 = pk(wf.w, wf.w);
    const ulonglong2* tc = (const ulonglong2*)(tp + TO);
    ulonglong2 q[(M3 + 1) / 2];
#pragma unroll
    for (int i = 0; i < (M3 + 1) / 2; i++) q[i] = tc[i];
#pragma unroll
    for (int k = 0; k < M3; k++) {
        ull tv = (k & 1) ? q[k >> 1].y : q[k >> 1].x;
        acc[0][KO+k] = fma2(w0, tv, acc[0][KO+k]);
        acc[1][KO+k] = fma2(w1, tv, acc[1][KO+k]);
        acc[2][KO+k] = fma2(w2, tv, acc[2][KO+k]);
        acc[3][KO+k] = fma2(w3, tv, acc[3][KO+k]);
    }
}

// ---------------- main fused kernel ----------------
__global__ void __launch_bounds__(128, 3)
tp_kernel(const float* __restrict__ x1_0, const float* __restrict__ x2_0,
          const float* __restrict__ x1_1, const float* __restrict__ x2_1,
          const float* __restrict__ x1_2, const float* __restrict__ x2_2,
          const float* __restrict__ C0,  const float* __restrict__ C1,
          const float* __restrict__ C2,  const float* __restrict__ C3,
          const float* __restrict__ C4,  const float* __restrict__ C5,
          const float* __restrict__ C6,  const float* __restrict__ C7,
          const float* __restrict__ C8,  const float* __restrict__ C9,
          const float* __restrict__ C10,
          float* __restrict__ out) {
    extern __shared__ ull sm[];
    ull* x1s = sm + X1_OFF;
    ull* x2s = sm + X2_OFF;
    ull* c2s = sm + C_OFF;
    ull* t2s = sm + T_OFF;
    const float* wsm = (const float*)(sm + W_OFF);
    const uint32_t wdst0 = s2u32(sm + W_OFF);

    const int tid   = threadIdx.x;
    const int zbase = blockIdx.x * ZT;
    const int ubase = blockIdx.y * UT;

    // ---- stage C (padded slots, dup into both f32x2 lanes) ----
    {
        const float* cps[NP] = {C0,C1,C2,C3,C4,C5,C6,C7,C8,C9,C10};
        for (int idx = tid; idx < C_TOT; idx += 128) {
            int p = 0;
#pragma unroll
            for (int q = 1; q < NP; q++) if (idx >= CPB[q]) p = q;
            int off  = idx - CPB[p];
            int m3   = 2*PL3[p] + 1;
            int slot = m3 + (m3 & 1);
            int mn   = off / slot;
            int k    = off % slot;
            float c  = (k < m3) ? cps[p][mn*m3 + k] : 0.0f;
            c2s[idx] = pk(c, c);
        }
    }
    // ---- stage x1s [ul*8+zp][10] ----
    for (int idx = tid; idx < UT*ZP*9; idx += 128) {
        int rec = idx / 9; int m = idx % 9;
        int ul = rec >> 3, zp = rec & 7;
        int u  = ubase + ul;
        int z0 = zbase + zp*2;
        float a, b;
        if (m == 0)      { a = x1_0[z0*64 + u];            b = x1_0[(z0+1)*64 + u]; }
        else if (m < 4)  { a = x1_1[(z0*64 + u)*3 + m-1];  b = x1_1[((z0+1)*64 + u)*3 + m-1]; }
        else             { a = x1_2[(z0*64 + u)*5 + m-4];  b = x1_2[((z0+1)*64 + u)*5 + m-4]; }
        x1s[rec*XSTR + m] = pk(a, b);
    }

    // thread identities
    const int zp  = tid & 7;
    const int grp = tid >> 6;          // Phase A path group (0/1)
    const int vlA = (tid >> 3) & 7;    // Phase A v-lane (0..7)
    const int wo  = tid >> 3;          // Phase B w-quad (0..15)

    ull acc[4][9];
#pragma unroll
    for (int j = 0; j < 4; j++)
#pragma unroll
        for (int k = 0; k < 9; k++) acc[j][k] = 0ull;

    for (int vc = 0; vc < NVC; vc++) {
        // ---- stage x2s chunk [vl*8+zp][10] ----
        for (int idx = tid; idx < VT*ZP*9; idx += 128) {
            int rec = idx / 9; int n = idx % 9;
            int vl = rec >> 3, zpp = rec & 7;
            int v  = vc*VT + vl;
            int z0 = zbase + zpp*2;
            float a, b;
            if (n == 0)      { a = x2_0[z0*64 + v];            b = x2_0[(z0+1)*64 + v]; }
            else if (n < 4)  { a = x2_1[(z0*64 + v)*3 + n-1];  b = x2_1[((z0+1)*64 + v)*3 + n-1]; }
            else             { a = x2_2[(z0*64 + v)*5 + n-4];  b = x2_2[((z0+1)*64 + v)*5 + n-4]; }
            x2s[rec*XSTR + n] = pk(a, b);
        }
        __syncthreads();

        for (int ul = 0; ul < UT; ul++) {
            const int u = ubase + ul;
            // ---- kick off W tile copy (8v x 11p x 64w floats = 22.5KB) ----
            {
                const float* gsrc = g_Wt + (size_t)((u << 6) + vc*VT) * (NP*64);
#pragma unroll
                for (int i = 0; i < 11; i++) {
                    int c = tid + i*128;
                    cpasync16(wdst0 + c*16, gsrc + c*4);
                }
                cpcommit();
            }
            // -------- Phase A (path-split across 2 groups) --------
            {
                ull a[10], b[10];
                const ulonglong2* ap = (const ulonglong2*)(x1s + (ul*ZP + zp)*XSTR);
                const ulonglong2* bp = (const ulonglong2*)(x2s + (vlA*ZP + zp)*XSTR);
#pragma unroll
                for (int i = 0; i < 5; i++) {
                    ulonglong2 qa = ap[i], qb = bp[i];
                    a[2*i] = qa.x; a[2*i+1] = qa.y;
                    b[2*i] = qb.x; b[2*i+1] = qb.y;
                }
                ull* trec = t2s + (vlA*ZP + zp)*TREC;
                if (grp == 0) {
                    pathA<0>(a, b, c2s, trec);
                    pathA<1>(a, b, c2s, trec);
                    pathA<3>(a, b, c2s, trec);
                    pathA<7>(a, b, c2s, trec);
                    pathA2<9,10>(a, b, c2s, trec);
                } else {
                    pathA<2>(a, b, c2s, trec);
                    pathA2<4,5>(a, b, c2s, trec);
                    pathA<6>(a, b, c2s, trec);
                    pathA<8>(a, b, c2s, trec);
                }
            }
            cpwait0();
            __syncthreads();
            // -------- Phase B --------
            {
                const float* wv = wsm + wo*4;
                const ull*   tp = t2s + zp*TREC;
#pragma unroll 1
                for (int vi = 0; vi < VT; vi++) {
                    pathB<0>(wv, tp, acc);
                    pathB<1>(wv, tp, acc);
                    pathB<2>(wv, tp, acc);
                    pathB<3>(wv, tp, acc);
                    pathB<4>(wv, tp, acc);
                    pathB<5>(wv, tp, acc);
                    pathB<6>(wv, tp, acc);
                    pathB<7>(wv, tp, acc);
                    pathB<8>(wv, tp, acc);
                    pathB<9>(wv, tp, acc);
                    pathB<10>(wv, tp, acc);
                    wv += NP*64;       // next v in W tile
                    tp += ZP*TREC;     // next vl record
                }
            }
            __syncthreads();
        }
    }

    // ---- epilogue: combine u-splits via atomics ----
    const int z0 = zbase + zp*2;
#pragma unroll
    for (int j = 0; j < 4; j++) {
        const int w = wo*4 + j;
#pragma unroll
        for (int k = 0; k < 9; k++) {
            float lo, hi;
            unpk(acc[j][k], lo, hi);
            atomicAdd(&out[(z0*64 + w)*9 + k], lo);
            atomicAdd(&out[((z0+1)*64 + w)*9 + k], hi);
        }
    }
}

// ---------------------------------------------------------------------------
extern "C" void kernel_launch(void* const* d_in, const int* in_sizes, int n_in,
                              void* d_out, int out_size) {
    const float* x1_0 = (const float*)d_in[0];
    const float* x2_0 = (const float*)d_in[1];
    const float* x1_1 = (const float*)d_in[2];
    const float* x2_1 = (const float*)d_in[3];
    const float* x1_2 = (const float*)d_in[4];
    const float* x2_2 = (const float*)d_in[5];
    const float* W    = (const float*)d_in[6];
    float* out = (float*)d_out;
    (void)in_sizes; (void)n_in;

    cudaFuncSetAttribute(tp_kernel, cudaFuncAttributeMaxDynamicSharedMemorySize, SMEM_BYTES);

    cudaMemsetAsync(d_out, 0, (size_t)out_size * sizeof(float), 0);

    int nW = 64 * 64 * NP * 64;
    transpose_W_kernel<<<nW / 256, 256>>>(W);

    dim3 grid(1024 / ZT, 64 / UT);   // (64, 8) = 512 blocks
    tp_kernel<<<grid, 128, SMEM_BYTES>>>(
        x1_0, x2_0, x1_1, x2_1, x1_2, x2_2,
        (const float*)d_in[7],  (const float*)d_in[8],  (const float*)d_in[9],
        (const float*)d_in[10], (const float*)d_in[11], (const float*)d_in[12],
        (const float*)d_in[13], (const float*)d_in[14], (const float*)d_in[15],
        (const float*)d_in[16], (const float*)d_in[17],
        out);
}

// round 7
// speedup vs baseline: 1.0022x; 1.0022x over previous
#include <cuda_runtime.h>
#include <stdint.h>

// ---------------------------------------------------------------------------
// HarmonicFullyConnectedTensorProduct (lmax=2, MUL=64, BATCH=1024, 11 paths)
// v4: W staged via cp.async into smem (latency off critical path),
//     Phase A slimmed (reg-cached a/b, paired C loads, merged-o paths,
//     path-split across thread groups), 3 CTAs/SM.
// ---------------------------------------------------------------------------

typedef unsigned long long ull;

#define NP 11
__host__ __device__ constexpr int PL1[NP]  = {0,0,0,1,1,1,1,2,2,2,2};
__host__ __device__ constexpr int PL2[NP]  = {0,1,2,0,1,1,2,0,1,2,2};
__host__ __device__ constexpr int PL3[NP]  = {0,1,2,1,0,2,1,2,1,0,2};
__host__ __device__ constexpr int XOFF[3]  = {0,1,4};
// t-record per-path blocks padded even (stride 46)
__host__ __device__ constexpr int TOP[NP]  = {0,2,6,12,16,18,24,28,34,38,40};
// padded C layout: per (m,n) slot = m3+(m3&1) ulls; path bases (ull units)
__host__ __device__ constexpr int CPB[NP]  = {0,2,14,44,56,74,128,188,218,278,328};
#define C_TOT 478

#define ZT 16
#define ZP 8
#define UT 8
#define VT 8
#define NVC 8
#define TREC 46
#define XSTR 10

// smem layout (ull units)
#define X1_OFF 0                    // 64 rec * 10 = 640
#define X2_OFF 640                  // 64 rec * 10 = 640
#define C_OFF  1280                 // 480 (478 used)
#define T_OFF  1760                 // 64 rec * 46 = 2944
#define W_OFF  4704                 // 2816 ull = 5632 floats
#define SMEM_ULL  7520
#define SMEM_BYTES (SMEM_ULL*8)     // 60160 -> 3 CTAs/SM

// W transposed: [u][v][p][w] floats
__device__ float g_Wt[64 * 64 * NP * 64];

// ---------------- packed f32x2 helpers ----------------
__device__ __forceinline__ ull pk(float lo, float hi) {
    ull r;
    asm("mov.b64 %0, {%1, %2};" : "=l"(r) : "r"(__float_as_uint(lo)), "r"(__float_as_uint(hi)));
    return r;
}
__device__ __forceinline__ void unpk(ull v, float& lo, float& hi) {
    unsigned a, b;
    asm("mov.b64 {%0, %1}, %2;" : "=r"(a), "=r"(b) : "l"(v));
    lo = __uint_as_float(a); hi = __uint_as_float(b);
}
__device__ __forceinline__ ull fma2(ull a, ull b, ull c) {
    ull d;
    asm("fma.rn.f32x2 %0, %1, %2, %3;" : "=l"(d) : "l"(a), "l"(b), "l"(c));
    return d;
}
__device__ __forceinline__ ull mul2(ull a, ull b) {
    ull d;
    asm("mul.rn.f32x2 %0, %1, %2;" : "=l"(d) : "l"(a), "l"(b));
    return d;
}
__device__ __forceinline__ uint32_t s2u32(const void* p) {
    uint32_t a;
    asm("{ .reg .u64 t; cvta.to.shared.u64 t, %1; cvt.u32.u64 %0, t; }" : "=r"(a) : "l"(p));
    return a;
}
__device__ __forceinline__ void cpasync16(uint32_t dst, const void* src) {
    asm volatile("cp.async.cg.shared.global [%0], [%1], 16;" :: "r"(dst), "l"(src));
}
__device__ __forceinline__ void cpcommit() {
    asm volatile("cp.async.commit_group;");
}
__device__ __forceinline__ void cpwait0() {
    asm volatile("cp.async.wait_group 0;" ::: "memory");
}

// ---------------- W transpose ----------------
__global__ void transpose_W_kernel(const float* __restrict__ W) {
    int idx = blockIdx.x * 256 + threadIdx.x;   // g_Wt index, w fastest
    int w  = idx & 63;
    int p  = (idx >> 6) % NP;
    int uv = idx / (NP * 64);
    g_Wt[idx] = W[(((p << 6) + w) << 12) + uv];
}

// ---------------- Phase A: single path ----------------
template <int P>
__device__ __forceinline__ void pathA(const ull* a, const ull* b,
                                      const ull* __restrict__ c2, ull* trec) {
    constexpr int L1 = PL1[P], L2 = PL2[P], L3 = PL3[P];
    constexpr int M1 = 2*L1+1, M2 = 2*L2+1, M3 = 2*L3+1;
    constexpr int O1 = XOFF[L1], O2 = XOFF[L2];
    constexpr int CB = CPB[P], SLOT = M3 + (M3 & 1), TO = TOP[P];
    ull t[M3];
#pragma unroll
    for (int k = 0; k < M3; k++) t[k] = 0ull;
#pragma unroll
    for (int m = 0; m < M1; m++) {
        ull am = a[O1 + m];
#pragma unroll
        for (int n = 0; n < M2; n++) {
            ull o = mul2(am, b[O2 + n]);
            const int base = CB + (m*M2 + n)*SLOT;
#pragma unroll
            for (int kk = 0; kk < M3/2; kk++) {
                ulonglong2 q = *(const ulonglong2*)(c2 + base + 2*kk);
                t[2*kk]   = fma2(o, q.x, t[2*kk]);
                t[2*kk+1] = fma2(o, q.y, t[2*kk+1]);
            }
            if (M3 & 1)
                t[M3-1] = fma2(o, c2[base + M3 - 1], t[M3-1]);
        }
    }
#pragma unroll
    for (int kk = 0; kk < M3/2; kk++) {
        ulonglong2 s; s.x = t[2*kk]; s.y = t[2*kk+1];
        *(ulonglong2*)(trec + TO + 2*kk) = s;
    }
    if (M3 & 1) {
        ulonglong2 s; s.x = t[M3-1]; s.y = t[M3-1];
        *(ulonglong2*)(trec + TO + M3 - 1) = s;
    }
}

// ---------------- Phase A: merged pair (PA has m3=1, PB has m3=5, same l1,l2) ----
template <int PA, int PB>
__device__ __forceinline__ void pathA2(const ull* a, const ull* b,
                                       const ull* __restrict__ c2, ull* trec) {
    constexpr int L1 = PL1[PA], L2 = PL2[PA];
    constexpr int M1 = 2*L1+1, M2 = 2*L2+1;
    constexpr int O1 = XOFF[L1], O2 = XOFF[L2];
    constexpr int CA = CPB[PA], CB = CPB[PB];
    ull tA = 0ull;
    ull tB[5] = {0ull,0ull,0ull,0ull,0ull};
#pragma unroll
    for (int m = 0; m < M1; m++) {
        ull am = a[O1 + m];
#pragma unroll
        for (int n = 0; n < M2; n++) {
            const int mn = m*M2 + n;
            ull o = mul2(am, b[O2 + n]);
            tA = fma2(o, c2[CA + mn*2], tA);
            const ull* cb = c2 + CB + mn*6;
            ulonglong2 q0 = *(const ulonglong2*)(cb);
            ulonglong2 q1 = *(const ulonglong2*)(cb + 2);
            ull c4 = cb[4];
            tB[0] = fma2(o, q0.x, tB[0]);
            tB[1] = fma2(o, q0.y, tB[1]);
            tB[2] = fma2(o, q1.x, tB[2]);
            tB[3] = fma2(o, q1.y, tB[3]);
            tB[4] = fma2(o, c4,  tB[4]);
        }
    }
    { ulonglong2 s; s.x = tA; s.y = tA; *(ulonglong2*)(trec + TOP[PA]) = s; }
    { ulonglong2 s; s.x = tB[0]; s.y = tB[1]; *(ulonglong2*)(trec + TOP[PB]    ) = s; }
    { ulonglong2 s; s.x = tB[2]; s.y = tB[3]; *(ulonglong2*)(trec + TOP[PB] + 2) = s; }
    { ulonglong2 s; s.x = tB[4]; s.y = tB[4]; *(ulonglong2*)(trec + TOP[PB] + 4) = s; }
}

// ---------------- Phase B: one path, 4 w per thread (W from smem) ----------------
template <int P>
__device__ __forceinline__ void pathB(const float* __restrict__ wv,
                                      const ull* __restrict__ tp,
                                      ull (&acc)[4][9]) {
    constexpr int M3 = 2*PL3[P]+1, TO = TOP[P], KO = XOFF[PL3[P]];
    float4 wf = *(const float4*)(wv + P * 64);
    ull w0 = pk(wf.x, wf.x);
    ull w1 = pk(wf.y, wf.y);
    ull w2 = pk(wf.z, wf.z);
    ull w3 = pk(wf.w, wf.w);
    const ulonglong2* tc = (const ulonglong2*)(tp + TO);
    ulonglong2 q[(M3 + 1) / 2];
#pragma unroll
    for (int i = 0; i < (M3 + 1) / 2; i++) q[i] = tc[i];
#pragma unroll
    for (int k = 0; k < M3; k++) {
        ull tv = (k & 1) ? q[k >> 1].y : q[k >> 1].x;
        acc[0][KO+k] = fma2(w0, tv, acc[0][KO+k]);
        acc[1][KO+k] = fma2(w1, tv, acc[1][KO+k]);
        acc[2][KO+k] = fma2(w2, tv, acc[2][KO+k]);
        acc[3][KO+k] = fma2(w3, tv, acc[3][KO+k]);
    }
}

// ---------------- main fused kernel ----------------
__global__ void __launch_bounds__(128, 3)
tp_kernel(const float* __restrict__ x1_0, const float* __restrict__ x2_0,
          const float* __restrict__ x1_1, const float* __restrict__ x2_1,
          const float* __restrict__ x1_2, const float* __restrict__ x2_2,
          const float* __restrict__ C0,  const float* __restrict__ C1,
          const float* __restrict__ C2,  const float* __restrict__ C3,
          const float* __restrict__ C4,  const float* __restrict__ C5,
          const float* __restrict__ C6,  const float* __restrict__ C7,
          const float* __restrict__ C8,  const float* __restrict__ C9,
          const float* __restrict__ C10,
          float* __restrict__ out) {
    extern __shared__ ull sm[];
    ull* x1s = sm + X1_OFF;
    ull* x2s = sm + X2_OFF;
    ull* c2s = sm + C_OFF;
    ull* t2s = sm + T_OFF;
    const float* wsm = (const float*)(sm + W_OFF);
    const uint32_t wdst0 = s2u32(sm + W_OFF);

    const int tid   = threadIdx.x;
    const int zbase = blockIdx.x * ZT;
    const int ubase = blockIdx.y * UT;

    // ---- stage C (padded slots, dup into both f32x2 lanes) ----
    {
        const float* cps[NP] = {C0,C1,C2,C3,C4,C5,C6,C7,C8,C9,C10};
        for (int idx = tid; idx < C_TOT; idx += 128) {
            int p = 0;
#pragma unroll
            for (int q = 1; q < NP; q++) if (idx >= CPB[q]) p = q;
            int off  = idx - CPB[p];
            int m3   = 2*PL3[p] + 1;
            int slot = m3 + (m3 & 1);
            int mn   = off / slot;
            int k    = off % slot;
            float c  = (k < m3) ? cps[p][mn*m3 + k] : 0.0f;
            c2s[idx] = pk(c, c);
        }
    }
    // ---- stage x1s [ul*8+zp][10] ----
    for (int idx = tid; idx < UT*ZP*9; idx += 128) {
        int rec = idx / 9; int m = idx % 9;
        int ul = rec >> 3, zp = rec & 7;
        int u  = ubase + ul;
        int z0 = zbase + zp*2;
        float a, b;
        if (m == 0)      { a = x1_0[z0*64 + u];            b = x1_0[(z0+1)*64 + u]; }
        else if (m < 4)  { a = x1_1[(z0*64 + u)*3 + m-1];  b = x1_1[((z0+1)*64 + u)*3 + m-1]; }
        else             { a = x1_2[(z0*64 + u)*5 + m-4];  b = x1_2[((z0+1)*64 + u)*5 + m-4]; }
        x1s[rec*XSTR + m] = pk(a, b);
    }

    // thread identities
    const int zp  = tid & 7;
    const int grp = tid >> 6;          // Phase A path group (0/1)
    const int vlA = (tid >> 3) & 7;    // Phase A v-lane (0..7)
    const int wo  = tid >> 3;          // Phase B w-quad (0..15)

    ull acc[4][9];
#pragma unroll
    for (int j = 0; j < 4; j++)
#pragma unroll
        for (int k = 0; k < 9; k++) acc[j][k] = 0ull;

    for (int vc = 0; vc < NVC; vc++) {
        // ---- stage x2s chunk [vl*8+zp][10] ----
        for (int idx = tid; idx < VT*ZP*9; idx += 128) {
            int rec = idx / 9; int n = idx % 9;
            int vl = rec >> 3, zpp = rec & 7;
            int v  = vc*VT + vl;
            int z0 = zbase + zpp*2;
            float a, b;
            if (n == 0)      { a = x2_0[z0*64 + v];            b = x2_0[(z0+1)*64 + v]; }
            else if (n < 4)  { a = x2_1[(z0*64 + v)*3 + n-1];  b = x2_1[((z0+1)*64 + v)*3 + n-1]; }
            else             { a = x2_2[(z0*64 + v)*5 + n-4];  b = x2_2[((z0+1)*64 + v)*5 + n-4]; }
            x2s[rec*XSTR + n] = pk(a, b);
        }
        __syncthreads();

        for (int ul = 0; ul < UT; ul++) {
            const int u = ubase + ul;
            // ---- kick off W tile copy (8v x 11p x 64w floats = 22.5KB) ----
            {
                const float* gsrc = g_Wt + (size_t)((u << 6) + vc*VT) * (NP*64);
#pragma unroll
                for (int i = 0; i < 11; i++) {
                    int c = tid + i*128;
                    cpasync16(wdst0 + c*16, gsrc + c*4);
                }
                cpcommit();
            }
            // -------- Phase A (path-split across 2 groups) --------
            {
                ull a[10], b[10];
                const ulonglong2* ap = (const ulonglong2*)(x1s + (ul*ZP + zp)*XSTR);
                const ulonglong2* bp = (const ulonglong2*)(x2s + (vlA*ZP + zp)*XSTR);
#pragma unroll
                for (int i = 0; i < 5; i++) {
                    ulonglong2 qa = ap[i], qb = bp[i];
                    a[2*i] = qa.x; a[2*i+1] = qa.y;
                    b[2*i] = qb.x; b[2*i+1] = qb.y;
                }
                ull* trec = t2s + (vlA*ZP + zp)*TREC;
                if (grp == 0) {
                    pathA<0>(a, b, c2s, trec);
                    pathA<1>(a, b, c2s, trec);
                    pathA<3>(a, b, c2s, trec);
                    pathA<7>(a, b, c2s, trec);
                    pathA2<9,10>(a, b, c2s, trec);
                } else {
                    pathA<2>(a, b, c2s, trec);
                    pathA2<4,5>(a, b, c2s, trec);
                    pathA<6>(a, b, c2s, trec);
                    pathA<8>(a, b, c2s, trec);
                }
            }
            cpwait0();
            __syncthreads();
            // -------- Phase B --------
            {
                const float* wv = wsm + wo*4;
                const ull*   tp = t2s + zp*TREC;
#pragma unroll 1
                for (int vi = 0; vi < VT; vi++) {
                    pathB<0>(wv, tp, acc);
                    pathB<1>(wv, tp, acc);
                    pathB<2>(wv, tp, acc);
                    pathB<3>(wv, tp, acc);
                    pathB<4>(wv, tp, acc);
                    pathB<5>(wv, tp, acc);
                    pathB<6>(wv, tp, acc);
                    pathB<7>(wv, tp, acc);
                    pathB<8>(wv, tp, acc);
                    pathB<9>(wv, tp, acc);
                    pathB<10>(wv, tp, acc);
                    wv += NP*64;       // next v in W tile
                    tp += ZP*TREC;     // next vl record
                }
            }
            __syncthreads();
        }
    }

    // ---- epilogue: combine u-splits via atomics ----
    const int z0 = zbase + zp*2;
#pragma unroll
    for (int j = 0; j < 4; j++) {
        const int w = wo*4 + j;
#pragma unroll
        for (int k = 0; k < 9; k++) {
            float lo, hi;
            unpk(acc[j][k], lo, hi);
            atomicAdd(&out[(z0*64 + w)*9 + k], lo);
            atomicAdd(&out[((z0+1)*64 + w)*9 + k], hi);
        }
    }
}

// ---------------------------------------------------------------------------
extern "C" void kernel_launch(void* const* d_in, const int* in_sizes, int n_in,
                              void* d_out, int out_size) {
    const float* x1_0 = (const float*)d_in[0];
    const float* x2_0 = (const float*)d_in[1];
    const float* x1_1 = (const float*)d_in[2];
    const float* x2_1 = (const float*)d_in[3];
    const float* x1_2 = (const float*)d_in[4];
    const float* x2_2 = (const float*)d_in[5];
    const float* W    = (const float*)d_in[6];
    float* out = (float*)d_out;
    (void)in_sizes; (void)n_in;

    cudaFuncSetAttribute(tp_kernel, cudaFuncAttributeMaxDynamicSharedMemorySize, SMEM_BYTES);

    cudaMemsetAsync(d_out, 0, (size_t)out_size * sizeof(float), 0);

    int nW = 64 * 64 * NP * 64;
    transpose_W_kernel<<<nW / 256, 256>>>(W);

    dim3 grid(1024 / ZT, 64 / UT);   // (64, 8) = 512 blocks
    tp_kernel<<<grid, 128, SMEM_BYTES>>>(
        x1_0, x2_0, x1_1, x2_1, x1_2, x2_2,
        (const float*)d_in[7],  (const float*)d_in[8],  (const float*)d_in[9],
        (const float*)d_in[10], (const float*)d_in[11], (const float*)d_in[12],
        (const float*)d_in[13], (const float*)d_in[14], (const float*)d_in[15],
        (const float*)d_in[16], (const float*)d_in[17],
        out);
}